// round 14
// baseline (speedup 1.0000x reference)
#include <cuda_runtime.h>

#define G_ 4
#define T_ 2048
#define E_ 8
#define D_ 1024
#define C_ 2048
#define NTOK (G_ * T_)
#define NTOT ((long long)G_ * T_ * E_ * C_)

__device__ float g_probs[G_ * E_ * T_];   // expert-major probs
__device__ float g_zt[NTOK];              // per-token z partials
__device__ float g_zsum;                  // reduced sum (written by topk)
__device__ int   g_tok [G_ * E_ * C_];    // rank table: token index or -1
__device__ float g_gate[G_ * E_ * C_];    // rank table: gate value

// ---------------------------------------------------------------------------
// Kernel 1: router. 1 token/warp, W staged in TWO 16 KB halves so smem
// (16.5 KB) and regs (~40) both allow 6 blocks/SM -> ~75% occupancy
// (r13 variant was RF-capped at 3 blocks/SM, occ 36.6%, latency-bound).
// ---------------------------------------------------------------------------
__global__ void __launch_bounds__(256)
router_kernel(const float* __restrict__ x,
              const float* __restrict__ W,
              const float* __restrict__ b) {
    __shared__ __align__(16) float sW[4 * D_];   // 16 KB: 4 experts per pass
    __shared__ float sb[E_];

    int warp = threadIdx.x >> 5;
    int lane = threadIdx.x & 31;
    int token = blockIdx.x * 8 + warp;        // 0 .. NTOK-1
    int g = token / T_;
    int t = token % T_;
    const float4* x4 = reinterpret_cast<const float4*>(x + (long long)token * D_);

    if (threadIdx.x < E_) sb[threadIdx.x] = b[threadIdx.x];

    float logit[E_];

    #pragma unroll
    for (int pass = 0; pass < 2; pass++) {
        __syncthreads();                      // safe to (re)stage sW
        for (int i = threadIdx.x; i < 4 * D_ / 4; i += 256)
            reinterpret_cast<float4*>(sW)[i] =
                reinterpret_cast<const float4*>(W + pass * 4 * D_)[i];
        __syncthreads();

        float acc[4];
        #pragma unroll
        for (int e = 0; e < 4; e++) acc[e] = 0.f;

        #pragma unroll
        for (int i = 0; i < D_ / (32 * 4); i++) {   // 8 iterations
            int d4 = i * 32 + lane;
            float4 xv = x4[d4];                      // pass 1: L1 hit
            #pragma unroll
            for (int e = 0; e < 4; e++) {
                float4 wv = reinterpret_cast<const float4*>(sW + e * D_)[d4];
                acc[e] += xv.x * wv.x + xv.y * wv.y + xv.z * wv.z + xv.w * wv.w;
            }
        }
        #pragma unroll
        for (int o = 16; o > 0; o >>= 1)
            #pragma unroll
            for (int e = 0; e < 4; e++)
                acc[e] += __shfl_xor_sync(0xffffffffu, acc[e], o);
        #pragma unroll
        for (int e = 0; e < 4; e++)
            logit[pass * 4 + e] = acc[e] + sb[pass * 4 + e];
    }

    // every lane holds all 8 logits
    float m = -1e30f;
    #pragma unroll
    for (int e = 0; e < E_; e++) m = fmaxf(m, logit[e]);
    float ex[E_], sum = 0.f;
    #pragma unroll
    for (int e = 0; e < E_; e++) { ex[e] = expf(logit[e] - m); sum += ex[e]; }
    float inv = 1.f / sum;
    float lse = m + logf(sum);

    if (lane < E_)
        g_probs[(g * E_ + lane) * T_ + t] = ex[lane] * inv;
    if (lane == 0) {
        float zt = 0.f;
        #pragma unroll
        for (int e = 0; e < E_; e++) {
            float ls = logit[e] - lse;
            zt += ls * ls;
        }
        g_zt[token] = zt;
    }
}

// ---------------------------------------------------------------------------
// Kernel 2 (r13 winner, ~8 us): topk via register/shuffle bitonic sort.
// Thread t holds {2t, 2t+1} in registers; 15 shared stages, 40 shfl stages,
// 11 intra-thread. Descending => prob desc, idx asc on ties (lax.top_k).
// ---------------------------------------------------------------------------
__global__ void topk_kernel() {
    __shared__ unsigned long long s[T_];   // 16 KB (shared stages only)
    __shared__ float red[1024];

    int ge = blockIdx.x;                   // 0..31
    int e = ge % E_;
    int t = threadIdx.x;                   // 0..1023
    int lane = t & 31;
    int i0 = 2 * t, i1 = 2 * t + 1;

    const float* p = g_probs + (long long)ge * T_;
    unsigned long long e0 =
        ((unsigned long long)__float_as_uint(p[i0]) << 32) | (unsigned int)(~i0);
    unsigned long long e1 =
        ((unsigned long long)__float_as_uint(p[i1]) << 32) | (unsigned int)(~i1);

    #pragma unroll
    for (int k = 2; k <= T_; k <<= 1) {
        bool desc = ((i0 & k) == 0);

        for (int j = k >> 1; j >= 64; j >>= 1) {
            s[i0] = e0; s[i1] = e1;
            __syncthreads();
            unsigned long long p0 = s[i0 ^ j], p1 = s[i1 ^ j];
            bool lower = ((i0 & j) == 0);
            bool keepmax = (desc == lower);
            e0 = keepmax ? (e0 > p0 ? e0 : p0) : (e0 < p0 ? e0 : p0);
            e1 = keepmax ? (e1 > p1 ? e1 : p1) : (e1 < p1 ? e1 : p1);
            __syncthreads();
        }
        #pragma unroll
        for (int j = (k >> 1) >= 32 ? 32 : (k >> 1); j >= 2; j >>= 1) {
            unsigned long long p0 = __shfl_xor_sync(0xffffffffu, e0, j >> 1);
            unsigned long long p1 = __shfl_xor_sync(0xffffffffu, e1, j >> 1);
            bool lower = ((lane & (j >> 1)) == 0);
            bool keepmax = (desc == lower);
            e0 = keepmax ? (e0 > p0 ? e0 : p0) : (e0 < p0 ? e0 : p0);
            e1 = keepmax ? (e1 > p1 ? e1 : p1) : (e1 < p1 ? e1 : p1);
        }
        {
            unsigned long long mx = (e0 > e1) ? e0 : e1;
            unsigned long long mn = (e0 > e1) ? e1 : e0;
            e0 = desc ? mx : mn;
            e1 = desc ? mn : mx;
        }
    }

    const int caps[E_] = {512, 512, 256, 256, 128, 128, 128, 128};
    int cap = caps[e];

    if (i0 < cap) {
        g_gate[ge * C_ + i0] = __uint_as_float((unsigned int)(e0 >> 32));
        g_tok [ge * C_ + i0] = (int)(~(unsigned int)(e0 & 0xffffffffu));
    } else {
        g_gate[ge * C_ + i0] = 0.f;
        g_tok [ge * C_ + i0] = -1;
    }
    if (i1 < cap) {
        g_gate[ge * C_ + i1] = __uint_as_float((unsigned int)(e1 >> 32));
        g_tok [ge * C_ + i1] = (int)(~(unsigned int)(e1 & 0xffffffffu));
    } else {
        g_gate[ge * C_ + i1] = 0.f;
        g_tok [ge * C_ + i1] = -1;
    }

    if (blockIdx.x == 0) {
        float acc = 0.f;
        for (int i = t; i < NTOK; i += 1024)
            acc += g_zt[i];
        red[t] = acc;
        __syncthreads();
        for (int o = 512; o > 0; o >>= 1) {
            if (t < o) red[t] += red[t + o];
            __syncthreads();
        }
        if (t == 0) g_zsum = red[0];
    }
}

// ---------------------------------------------------------------------------
// Kernel 3 (r13 winner, ~150 us at ~7.1 TB/s): fused materialize.
// Block = (g, e, c-half, 16-token chunk); table slice in registers.
// ---------------------------------------------------------------------------
__global__ void materialize_kernel(float* __restrict__ out) {
    int B = blockIdx.x;
    int tch   = B & 127;
    int rest  = B >> 7;
    int chalf = rest & 1;
    int ge    = rest >> 1;
    int e = ge & 7;
    int g = ge >> 3;

    int c4 = chalf * 256 + threadIdx.x;
    int4   tok4  = reinterpret_cast<const int4*  >(g_tok )[ge * (C_ / 4) + c4];
    float4 gate4 = reinterpret_cast<const float4*>(g_gate)[ge * (C_ / 4) + c4];

    const long long NTOT4 = NTOT / 4;
    float4* out4 = reinterpret_cast<float4*>(out);

    int tbase = tch * 16;
    #pragma unroll
    for (int i = 0; i < 16; i++) {
        int t = tbase + i;
        long long off = (((long long)g * T_ + t) * E_ + e) * (C_ / 4) + c4;
        float4 d, c;
        d.x = (tok4.x == t) ? 1.f : 0.f;  c.x = (tok4.x == t) ? gate4.x : 0.f;
        d.y = (tok4.y == t) ? 1.f : 0.f;  c.y = (tok4.y == t) ? gate4.y : 0.f;
        d.z = (tok4.z == t) ? 1.f : 0.f;  c.z = (tok4.z == t) ? gate4.z : 0.f;
        d.w = (tok4.w == t) ? 1.f : 0.f;  c.w = (tok4.w == t) ? gate4.w : 0.f;
        out4[off]         = d;   // dispatch_mask
        out4[off + NTOT4] = c;   // combine_array
    }

    if (B == 0 && threadIdx.x == 0)
        out[2 * NTOT] = g_zsum / (float)(G_ * T_ * E_);   // router_z_loss
}

extern "C" void kernel_launch(void* const* d_in, const int* in_sizes, int n_in,
                              void* d_out, int out_size) {
    const float* x = (const float*)d_in[0];   // token_inputs [G,T,D]
    const float* W = (const float*)d_in[1];   // [E,D]
    const float* b = (const float*)d_in[2];   // [E]
    float* out = (float*)d_out;

    router_kernel<<<NTOK / 8, 256>>>(x, W, b);
    topk_kernel<<<G_ * E_, 1024>>>();
    materialize_kernel<<<G_ * E_ * 2 * (T_ / 16), 256>>>(out);
}